// round 16
// baseline (speedup 1.0000x reference)
#include <cuda_runtime.h>
#include <cuda_fp16.h>
#include <cstdint>

// Decoder LSTM: B=128, H=1024, T=256, OUT=1, IN=2.
// Persistent kernel, 128 CTAs x 256 thr (8 warps). R13 structure:
// CTA (bg=cta>>6, ng=cta&63): batch rows [bg*64,+64) x hidden units [ng*16,+16)
// (64 gate rows of W_hh in SMEM fp16). Warp (rtp 0..1, kq 0..3): 2 rt tiles x
// 64 N x k-quarter; one B ldsm feeds both rt tiles. kq0 warps do tail.
// R15 deltas: zero-acc GEMM with bias+feedback folded into the tail,
// tanh.approx.f32 pointwise, flag-based (release/acquire) group barrier.

#define NCTA 128
#define NTHR 256
#define HID 1024
#define BSZ 128
#define KP 1032   // padded K stride (fp16 elems) for W in SMEM

#define W_BYTES (64 * KP * 2)
#define CONST_BYTES 1024
#define RED_BYTES (2 * 3 * 2 * 8 * 32 * 16)
#define SMEM_BYTES (W_BYTES + CONST_BYTES + RED_BYTES)

// h in A-fragment layout (fp16x2): [rt 0..7][kt 0..63][lane 0..31][reg 0..3]
__device__ uint32_t g_frag[2][8 * 64 * 32 * 4];
__device__ unsigned int g_bar_count[64];   // legacy atomic barrier (startup)
__device__ unsigned int g_bar_gen[64];
__device__ unsigned int g_flag[2][64];     // per-CTA arrival generation

__device__ __forceinline__ float tanh_hw(float x) {
    float y;
    asm("tanh.approx.f32 %0, %1;" : "=f"(y) : "f"(x));
    return y;
}
__device__ __forceinline__ float sig_hw(float x) {
    return fmaf(tanh_hw(0.5f * x), 0.5f, 0.5f);
}

__device__ __forceinline__ void mma_f16(float* c, const uint4& a, uint32_t b0, uint32_t b1) {
    asm volatile(
        "mma.sync.aligned.m16n8k16.row.col.f32.f16.f16.f32 "
        "{%0,%1,%2,%3},{%4,%5,%6,%7},{%8,%9},{%0,%1,%2,%3};\n"
        : "+f"(c[0]), "+f"(c[1]), "+f"(c[2]), "+f"(c[3])
        : "r"(a.x), "r"(a.y), "r"(a.z), "r"(a.w), "r"(b0), "r"(b1));
}

__device__ __forceinline__ void ldsm_x4(uint32_t& r0, uint32_t& r1, uint32_t& r2,
                                        uint32_t& r3, uint32_t saddr) {
    asm volatile("ldmatrix.sync.aligned.m8n8.x4.shared.b16 {%0,%1,%2,%3}, [%4];\n"
                 : "=r"(r0), "=r"(r1), "=r"(r2), "=r"(r3) : "r"(saddr));
}

__device__ __forceinline__ uint32_t packh2(float a, float b) {
    __half2 p = __floats2half2_rn(a, b);
    return *(uint32_t*)&p;
}

// startup barrier (atomic counter; self-resetting, gen-monotone across launches)
__device__ __forceinline__ void grid_barrier_atomic(int grp) {
    __threadfence();
    __syncthreads();
    if (threadIdx.x == 0) {
        volatile unsigned int* vgen = &g_bar_gen[grp * 32];
        unsigned int g = *vgen;
        unsigned int arrived = atomicAdd(&g_bar_count[grp * 32], 1u);
        if (arrived == 63) {
            g_bar_count[grp * 32] = 0;
            __threadfence();
            atomicExch((unsigned int*)&g_bar_gen[grp * 32], g + 1u);
        } else {
            while (*vgen == g) {}
        }
        __threadfence();
    }
    __syncthreads();
}

// in-loop barrier: release-store own flag = gen; 1 warp acquire-polls all 64
__device__ __forceinline__ void grid_barrier_flag(int grp, int ng, unsigned int gen) {
    __threadfence();
    __syncthreads();
    if (threadIdx.x == 0) {
        unsigned int* fl = &g_flag[grp][ng];
        asm volatile("st.global.release.gpu.u32 [%0], %1;" :: "l"(fl), "r"(gen) : "memory");
    }
    if (threadIdx.x < 32) {
        const unsigned int* p0 = &g_flag[grp][threadIdx.x];
        const unsigned int* p1 = &g_flag[grp][threadIdx.x + 32];
        unsigned int v0, v1;
        do {
            asm volatile("ld.global.acquire.gpu.u32 %0, [%1];" : "=r"(v0) : "l"(p0) : "memory");
            asm volatile("ld.global.acquire.gpu.u32 %0, [%1];" : "=r"(v1) : "l"(p1) : "memory");
        } while (__any_sync(0xffffffffu, (v0 < gen) | (v1 < gen)));
    }
    __syncthreads();
}

extern __shared__ char smem_raw[];

__global__ __launch_bounds__(NTHR, 1) void decoder_kernel(
    const float* __restrict__ h0, const float* __restrict__ c0,
    const float* __restrict__ Wih, const float* __restrict__ Whh,
    const float* __restrict__ bih, const float* __restrict__ bhh,
    const float* __restrict__ Wlin, const float* __restrict__ blin,
    float* __restrict__ out, int T)
{
    __half* ws = (__half*)smem_raw;                       // [64][KP] W slice
    float* cc0 = (float*)(smem_raw + W_BYTES);            // bias (t=0)    [64]
    float* cc1 = cc0 + 64;                                // bias+Wih[:,1] [64]
    float* wi0 = cc1 + 64;                                // Wih[:,0]      [64]
    float* wl  = wi0 + 64;                                // Wlin slice    [16]
    float* red = (float*)(smem_raw + W_BYTES + CONST_BYTES);

    const int cta  = blockIdx.x;
    const int bg   = cta >> 6;       // batch half / barrier group
    const int ng   = cta & 63;       // hidden group (16 units)
    const int tid  = threadIdx.x;
    const int w    = tid >> 5;
    const int rtp  = w & 1;          // rt pair (2 tiles of 16 rows)
    const int kq   = w >> 1;         // k quarter
    const int lane = tid & 31;
    const int gi   = lane >> 2;
    const int tq   = lane & 3;

    // ---------------- init ----------------
    for (int idx = tid; idx < 64 * HID; idx += NTHR) {
        int n = idx >> 10;
        int k = idx & (HID - 1);
        int row = ((n >> 4) << 10) + (ng << 4) + (n & 15);
        ws[n * KP + k] = __float2half_rn(Whh[row * HID + k]);
    }
    if (tid < 64) {
        int n = tid;
        int row = ((n >> 4) << 10) + (ng << 4) + (n & 15);
        float bb = bih[row] + bhh[row];
        cc0[n] = bb;
        cc1[n] = bb + Wih[row * 2 + 1];
        wi0[n] = Wih[row * 2 + 0];
    }
    if (tid < 16) wl[tid] = Wlin[(ng << 4) + tid];

    // h0 -> fragment buffer 0 (CTA c converts batch row c; same bg group)
    for (int p = tid; p < HID / 2; p += NTHR) {
        int k0 = p << 1;
        float a = h0[cta * HID + k0], b = h0[cta * HID + k0 + 1];
        int rtt = cta >> 4, kt = k0 >> 4;
        int lanep = (cta & 7) * 4 + ((k0 >> 1) & 3);
        int reg = ((cta >> 3) & 1) + 2 * ((k0 >> 3) & 1);
        g_frag[0][((rtt * 64 + kt) * 32 + lanep) * 4 + reg] = packh2(a, b);
    }
    for (int t = tid; t < T; t += NTHR) out[cta * T + t] = 0.0f;
    if (tid == 0) g_flag[bg][ng] = 0u;   // reset flag barrier for this launch

    // rows: row(r, rh) = bg*64 + rtp*32 + r*16 + rh*8 + gi
    const int rowbase = bg * 64 + (rtp << 5);

    // creg (kq==0 warps own both tiles' tails, as in R13)
    float creg[2][2][4];
    if (kq == 0) {
#pragma unroll
        for (int r = 0; r < 2; ++r)
#pragma unroll
            for (int rh = 0; rh < 2; ++rh)
#pragma unroll
                for (int q = 0; q < 4; ++q) {
                    int u = (q >> 1) * 8 + (tq << 1) + (q & 1);
                    creg[r][rh][q] =
                        c0[(rowbase + r * 16 + rh * 8 + gi) * HID + (ng << 4) + u];
                }
    } else {
#pragma unroll
        for (int r = 0; r < 2; ++r)
#pragma unroll
            for (int rh = 0; rh < 2; ++rh)
#pragma unroll
                for (int q = 0; q < 4; ++q) creg[r][rh][q] = 0.0f;
    }
    const float blin0 = blin[0];

    // ldsm bases
    const int m_ = lane >> 3;
    const int r_ = lane & 7;
    const uint32_t s_w = (uint32_t)__cvta_generic_to_shared(ws);
    uint32_t sb[4];
#pragma unroll
    for (int g2 = 0; g2 < 4; ++g2) {
        int wrow = g2 * 16 + ((m_ >> 1) << 3) + r_;
        sb[g2] = s_w + (wrow * KP + ((m_ & 1) << 3)) * 2;
    }

    const int g_rt0  = bg * 4 + rtp * 2;
    const int abase0 = g_rt0 * 8192 + (kq << 4) * 128 + lane * 4;
    const int abase1 = abase0 + 8192;

    grid_barrier_atomic(bg);   // flags now reset everywhere; start stepping

    // ---------------- time loop ----------------
    for (int t = 0; t < T; ++t) {
        const uint32_t* A = g_frag[t & 1];
        uint32_t* N = g_frag[(t + 1) & 1];

        // feedback loads first (long latency, consumed only in the tail)
        float op[2][2];
        if (kq == 0 && t > 0) {
#pragma unroll
            for (int r = 0; r < 2; ++r)
#pragma unroll
                for (int rh = 0; rh < 2; ++rh)
                    op[r][rh] = __ldcg(
                        &out[(rowbase + r * 16 + rh * 8 + gi) * T + t - 1]);
        } else {
            op[0][0] = op[0][1] = op[1][0] = op[1][1] = 0.0f;
        }

        // zero-acc GEMM (uniform across warps)
        float acc0[8][4], acc1[8][4];
#pragma unroll
        for (int nb = 0; nb < 8; ++nb)
#pragma unroll
            for (int ci = 0; ci < 4; ++ci) { acc0[nb][ci] = 0.f; acc1[nb][ci] = 0.f; }

#pragma unroll 4
        for (int i = 0; i < 16; ++i) {
            uint4 a0 = __ldcg((const uint4*)(A + abase0 + i * 128));
            uint4 a1 = __ldcg((const uint4*)(A + abase1 + i * 128));
            uint32_t so = ((kq << 4) + i) * 32;
#pragma unroll
            for (int g2 = 0; g2 < 4; ++g2) {
                uint32_t b0, b1, b2, b3;
                ldsm_x4(b0, b1, b2, b3, sb[g2] + so);
                mma_f16(acc0[2 * g2],     a0, b0, b1);
                mma_f16(acc0[2 * g2 + 1], a0, b2, b3);
                mma_f16(acc1[2 * g2],     a1, b0, b1);
                mma_f16(acc1[2 * g2 + 1], a1, b2, b3);
            }
        }

        // merge k-quarter partials (layout as R13: [rtp][kq-1][r][nb][lane] f4)
        if (kq > 0) {
            float* d = red + ((((rtp * 3 + (kq - 1)) * 2) * 8) * 32 + lane) * 4;
#pragma unroll
            for (int nb = 0; nb < 8; ++nb) {
                *(float4*)(d + nb * 128)        = *(float4*)acc0[nb];
                *(float4*)(d + 1024 + nb * 128) = *(float4*)acc1[nb];
            }
        }
        __syncthreads();

        if (kq == 0) {
#pragma unroll
            for (int q = 0; q < 3; ++q) {
                const float* s = red + ((((rtp * 3 + q) * 2) * 8) * 32 + lane) * 4;
#pragma unroll
                for (int nb = 0; nb < 8; ++nb) {
                    float4 x = *(const float4*)(s + nb * 128);
                    float4 y = *(const float4*)(s + 1024 + nb * 128);
                    acc0[nb][0] += x.x; acc0[nb][1] += x.y;
                    acc0[nb][2] += x.z; acc0[nb][3] += x.w;
                    acc1[nb][0] += y.x; acc1[nb][1] += y.y;
                    acc1[nb][2] += y.z; acc1[nb][3] += y.w;
                }
            }

            // fold bias + scalar feedback in the tail
            const float* cc = (t > 0) ? cc1 : cc0;
#pragma unroll
            for (int nb = 0; nb < 8; ++nb) {
                int g = nb >> 1, uh = nb & 1;
#pragma unroll
                for (int ci = 0; ci < 4; ++ci) {
                    int p = ci & 1, rh = ci >> 1;
                    int n = g * 16 + uh * 8 + (tq << 1) + p;
                    float add = cc[n];
                    acc0[nb][ci] += fmaf(op[0][rh], wi0[n], add);
                    acc1[nb][ci] += fmaf(op[1][rh], wi0[n], add);
                }
            }

            // pointwise LSTM (tanh.approx)
            float hv[2][2][4];
#pragma unroll
            for (int rh = 0; rh < 2; ++rh)
#pragma unroll
                for (int q = 0; q < 4; ++q) {
                    int uh = q >> 1, p = q & 1;
                    int ci = rh * 2 + p;
                    {
                        float cn = fmaf(sig_hw(acc0[2 + uh][ci]), creg[0][rh][q],
                                        sig_hw(acc0[0 + uh][ci]) * tanh_hw(acc0[4 + uh][ci]));
                        creg[0][rh][q] = cn;
                        hv[0][rh][q] = sig_hw(acc0[6 + uh][ci]) * tanh_hw(cn);
                    }
                    {
                        float cn = fmaf(sig_hw(acc1[2 + uh][ci]), creg[1][rh][q],
                                        sig_hw(acc1[0 + uh][ci]) * tanh_hw(acc1[4 + uh][ci]));
                        creg[1][rh][q] = cn;
                        hv[1][rh][q] = sig_hw(acc1[6 + uh][ci]) * tanh_hw(cn);
                    }
                }

            // h store: one STG.128 per rt tile
#pragma unroll
            for (int r = 0; r < 2; ++r) {
                uint4 hp;
                hp.x = packh2(hv[r][0][0], hv[r][0][1]);
                hp.y = packh2(hv[r][1][0], hv[r][1][1]);
                hp.z = packh2(hv[r][0][2], hv[r][0][3]);
                hp.w = packh2(hv[r][1][2], hv[r][1][3]);
                *(uint4*)&N[(((g_rt0 + r) * 64 + ng) * 32 + lane) * 4] = hp;
            }

            // scalar head
#pragma unroll
            for (int r = 0; r < 2; ++r)
#pragma unroll
                for (int rh = 0; rh < 2; ++rh) {
                    float acc_s = 0.0f;
#pragma unroll
                    for (int q = 0; q < 4; ++q) {
                        int u = (q >> 1) * 8 + (tq << 1) + (q & 1);
                        acc_s = fmaf(hv[r][rh][q], wl[u], acc_s);
                    }
                    acc_s += __shfl_xor_sync(0xffffffffu, acc_s, 1);
                    acc_s += __shfl_xor_sync(0xffffffffu, acc_s, 2);
                    if (tq == 0) {
                        if (ng == 0) acc_s += blin0;
                        atomicAdd(&out[(rowbase + r * 16 + rh * 8 + gi) * T + t],
                                  acc_s);
                    }
                }
        }

        grid_barrier_flag(bg, ng, (unsigned int)(t + 1));
    }
}

extern "C" void kernel_launch(void* const* d_in, const int* in_sizes, int n_in,
                              void* d_out, int out_size) {
    const float* h0   = (const float*)d_in[0];
    const float* c0   = (const float*)d_in[1];
    const float* Wih  = (const float*)d_in[2];
    const float* Whh  = (const float*)d_in[3];
    const float* bih  = (const float*)d_in[4];
    const float* bhh  = (const float*)d_in[5];
    const float* Wlin = (const float*)d_in[6];
    const float* blin = (const float*)d_in[7];
    float* out = (float*)d_out;

    int T = out_size / BSZ;
    if (T <= 0) return;

    cudaFuncSetAttribute(decoder_kernel,
                         cudaFuncAttributeMaxDynamicSharedMemorySize, SMEM_BYTES);
    decoder_kernel<<<NCTA, NTHR, SMEM_BYTES>>>(h0, c0, Wih, Whh, bih, bhh,
                                               Wlin, blin, out, T);
}

// round 17
// speedup vs baseline: 1.6686x; 1.6686x over previous
#include <cuda_runtime.h>
#include <cuda_fp16.h>
#include <cstdint>

// Decoder LSTM: B=128, H=1024, T=256, OUT=1, IN=2.
// Persistent kernel, 128 CTAs x 256 thr (8 warps). R13 structure:
// CTA (bg=cta>>6, ng=cta&63): batch rows [bg*64,+64) x hidden units [ng*16,+16)
// (64 gate rows of W_hh in SMEM fp16). Warp (rtp 0..1, kq 0..3): 2 rt tiles x
// 64 N x k-quarter; one B ldsm feeds both rt tiles. kq0 warps do the tail.
// R16 deltas vs R13 (only the two changes proven safe in R15):
//   - bias + scalar feedback folded into the tail (feedback LDG issued at
//     loop top; GEMM starts from zero acc -> MMA chain no longer waits on L2)
//   - tanh.approx.f32 pointwise (tail MUFU halved; rel_err impact ~1e-6)
// Barrier: R13's single-atomic-counter per 64-CTA group (proven fastest).

#define NCTA 128
#define NTHR 256
#define HID 1024
#define BSZ 128
#define KP 1032   // padded K stride (fp16 elems) for W in SMEM

#define W_BYTES (64 * KP * 2)
#define CONST_BYTES 1024
#define RED_BYTES (2 * 3 * 2 * 8 * 32 * 16)
#define SMEM_BYTES (W_BYTES + CONST_BYTES + RED_BYTES)

// h in A-fragment layout (fp16x2): [rt 0..7][kt 0..63][lane 0..31][reg 0..3]
__device__ uint32_t g_frag[2][8 * 64 * 32 * 4];
__device__ unsigned int g_bar_count[64];   // [grp*32], 128B apart
__device__ unsigned int g_bar_gen[64];

__device__ __forceinline__ float tanh_hw(float x) {
    float y;
    asm("tanh.approx.f32 %0, %1;" : "=f"(y) : "f"(x));
    return y;
}
__device__ __forceinline__ float sig_hw(float x) {
    return fmaf(tanh_hw(0.5f * x), 0.5f, 0.5f);
}

__device__ __forceinline__ void mma_f16(float* c, const uint4& a, uint32_t b0, uint32_t b1) {
    asm volatile(
        "mma.sync.aligned.m16n8k16.row.col.f32.f16.f16.f32 "
        "{%0,%1,%2,%3},{%4,%5,%6,%7},{%8,%9},{%0,%1,%2,%3};\n"
        : "+f"(c[0]), "+f"(c[1]), "+f"(c[2]), "+f"(c[3])
        : "r"(a.x), "r"(a.y), "r"(a.z), "r"(a.w), "r"(b0), "r"(b1));
}

__device__ __forceinline__ void ldsm_x4(uint32_t& r0, uint32_t& r1, uint32_t& r2,
                                        uint32_t& r3, uint32_t saddr) {
    asm volatile("ldmatrix.sync.aligned.m8n8.x4.shared.b16 {%0,%1,%2,%3}, [%4];\n"
                 : "=r"(r0), "=r"(r1), "=r"(r2), "=r"(r3) : "r"(saddr));
}

__device__ __forceinline__ uint32_t packh2(float a, float b) {
    __half2 p = __floats2half2_rn(a, b);
    return *(uint32_t*)&p;
}

// 64-CTA group barrier (single atomic counter + broadcast spin; proven in R13)
__device__ __forceinline__ void grid_barrier(int grp) {
    __threadfence();
    __syncthreads();
    if (threadIdx.x == 0) {
        volatile unsigned int* vgen = &g_bar_gen[grp * 32];
        unsigned int g = *vgen;
        unsigned int arrived = atomicAdd(&g_bar_count[grp * 32], 1u);
        if (arrived == 63) {
            g_bar_count[grp * 32] = 0;
            __threadfence();
            atomicExch((unsigned int*)&g_bar_gen[grp * 32], g + 1u);
        } else {
            while (*vgen == g) {}
        }
        __threadfence();
    }
    __syncthreads();
}

extern __shared__ char smem_raw[];

__global__ __launch_bounds__(NTHR, 1) void decoder_kernel(
    const float* __restrict__ h0, const float* __restrict__ c0,
    const float* __restrict__ Wih, const float* __restrict__ Whh,
    const float* __restrict__ bih, const float* __restrict__ bhh,
    const float* __restrict__ Wlin, const float* __restrict__ blin,
    float* __restrict__ out, int T)
{
    __half* ws = (__half*)smem_raw;                       // [64][KP] W slice
    float* cc0 = (float*)(smem_raw + W_BYTES);            // bias (t=0)    [64]
    float* cc1 = cc0 + 64;                                // bias+Wih[:,1] [64]
    float* wi0 = cc1 + 64;                                // Wih[:,0]      [64]
    float* wl  = wi0 + 64;                                // Wlin slice    [16]
    float* red = (float*)(smem_raw + W_BYTES + CONST_BYTES);

    const int cta  = blockIdx.x;
    const int bg   = cta >> 6;       // batch half / barrier group
    const int ng   = cta & 63;       // hidden group (16 units)
    const int tid  = threadIdx.x;
    const int w    = tid >> 5;
    const int rtp  = w & 1;          // rt pair (2 tiles of 16 rows)
    const int kq   = w >> 1;         // k quarter
    const int lane = tid & 31;
    const int gi   = lane >> 2;
    const int tq   = lane & 3;

    // ---------------- init: W slice (64 gate rows) -> SMEM fp16 ----------------
    for (int idx = tid; idx < 64 * HID; idx += NTHR) {
        int n = idx >> 10;
        int k = idx & (HID - 1);
        int row = ((n >> 4) << 10) + (ng << 4) + (n & 15);
        ws[n * KP + k] = __float2half_rn(Whh[row * HID + k]);
    }
    if (tid < 64) {
        int n = tid;
        int row = ((n >> 4) << 10) + (ng << 4) + (n & 15);
        float bb = bih[row] + bhh[row];
        cc0[n] = bb;
        cc1[n] = bb + Wih[row * 2 + 1];
        wi0[n] = Wih[row * 2 + 0];
    }
    if (tid < 16) wl[tid] = Wlin[(ng << 4) + tid];

    // h0 -> fragment buffer 0 (CTA c converts batch row c; same bg group)
    for (int p = tid; p < HID / 2; p += NTHR) {
        int k0 = p << 1;
        float a = h0[cta * HID + k0], b = h0[cta * HID + k0 + 1];
        int rtt = cta >> 4, kt = k0 >> 4;
        int lanep = (cta & 7) * 4 + ((k0 >> 1) & 3);
        int reg = ((cta >> 3) & 1) + 2 * ((k0 >> 3) & 1);
        g_frag[0][((rtt * 64 + kt) * 32 + lanep) * 4 + reg] = packh2(a, b);
    }
    for (int t = tid; t < T; t += NTHR) out[cta * T + t] = 0.0f;

    // rows: row(r, rh) = bg*64 + rtp*32 + r*16 + rh*8 + gi
    const int rowbase = bg * 64 + (rtp << 5);

    // creg (kq==0 warps own both tiles' tails)
    float creg[2][2][4];
    if (kq == 0) {
#pragma unroll
        for (int r = 0; r < 2; ++r)
#pragma unroll
            for (int rh = 0; rh < 2; ++rh)
#pragma unroll
                for (int q = 0; q < 4; ++q) {
                    int u = (q >> 1) * 8 + (tq << 1) + (q & 1);
                    creg[r][rh][q] =
                        c0[(rowbase + r * 16 + rh * 8 + gi) * HID + (ng << 4) + u];
                }
    } else {
#pragma unroll
        for (int r = 0; r < 2; ++r)
#pragma unroll
            for (int rh = 0; rh < 2; ++rh)
#pragma unroll
                for (int q = 0; q < 4; ++q) creg[r][rh][q] = 0.0f;
    }
    const float blin0 = blin[0];

    // ldsm bases: group g2 covers W rows g2*16 .. +15 (n-tiles 2g2, 2g2+1)
    const int m_ = lane >> 3;
    const int r_ = lane & 7;
    const uint32_t s_w = (uint32_t)__cvta_generic_to_shared(ws);
    uint32_t sb[4];
#pragma unroll
    for (int g2 = 0; g2 < 4; ++g2) {
        int wrow = g2 * 16 + ((m_ >> 1) << 3) + r_;
        sb[g2] = s_w + (wrow * KP + ((m_ & 1) << 3)) * 2;
    }

    const int g_rt0  = bg * 4 + rtp * 2;                  // first global rt tile
    const int abase0 = g_rt0 * 8192 + (kq << 4) * 128 + lane * 4;
    const int abase1 = abase0 + 8192;

    grid_barrier(bg);

    // ---------------- time loop ----------------
    for (int t = 0; t < T; ++t) {
        const uint32_t* A = g_frag[t & 1];
        uint32_t* N = g_frag[(t + 1) & 1];

        // feedback loads first (long latency, consumed only in the tail)
        float op[2][2];
        if (kq == 0 && t > 0) {
#pragma unroll
            for (int r = 0; r < 2; ++r)
#pragma unroll
                for (int rh = 0; rh < 2; ++rh)
                    op[r][rh] = __ldcg(
                        &out[(rowbase + r * 16 + rh * 8 + gi) * T + t - 1]);
        } else {
            op[0][0] = op[0][1] = op[1][0] = op[1][1] = 0.0f;
        }

        // zero-acc GEMM (uniform across warps; MMA chain independent of L2)
        float acc0[8][4], acc1[8][4];
#pragma unroll
        for (int nb = 0; nb < 8; ++nb)
#pragma unroll
            for (int ci = 0; ci < 4; ++ci) { acc0[nb][ci] = 0.f; acc1[nb][ci] = 0.f; }

#pragma unroll 4
        for (int i = 0; i < 16; ++i) {
            uint4 a0 = __ldcg((const uint4*)(A + abase0 + i * 128));
            uint4 a1 = __ldcg((const uint4*)(A + abase1 + i * 128));
            uint32_t so = ((kq << 4) + i) * 32;
#pragma unroll
            for (int g2 = 0; g2 < 4; ++g2) {
                uint32_t b0, b1, b2, b3;
                ldsm_x4(b0, b1, b2, b3, sb[g2] + so);
                mma_f16(acc0[2 * g2],     a0, b0, b1);
                mma_f16(acc0[2 * g2 + 1], a0, b2, b3);
                mma_f16(acc1[2 * g2],     a1, b0, b1);
                mma_f16(acc1[2 * g2 + 1], a1, b2, b3);
            }
        }

        // merge k-quarter partials (layout: [rtp][kq-1][r][nb][lane] float4)
        if (kq > 0) {
            float* d = red + ((((rtp * 3 + (kq - 1)) * 2) * 8) * 32 + lane) * 4;
#pragma unroll
            for (int nb = 0; nb < 8; ++nb) {
                *(float4*)(d + nb * 128)        = *(float4*)acc0[nb];
                *(float4*)(d + 1024 + nb * 128) = *(float4*)acc1[nb];
            }
        }
        __syncthreads();

        if (kq == 0) {
#pragma unroll
            for (int q = 0; q < 3; ++q) {
                const float* s = red + ((((rtp * 3 + q) * 2) * 8) * 32 + lane) * 4;
#pragma unroll
                for (int nb = 0; nb < 8; ++nb) {
                    float4 x = *(const float4*)(s + nb * 128);
                    float4 y = *(const float4*)(s + 1024 + nb * 128);
                    acc0[nb][0] += x.x; acc0[nb][1] += x.y;
                    acc0[nb][2] += x.z; acc0[nb][3] += x.w;
                    acc1[nb][0] += y.x; acc1[nb][1] += y.y;
                    acc1[nb][2] += y.z; acc1[nb][3] += y.w;
                }
            }

            // fold bias + scalar feedback in the tail
            const float* cc = (t > 0) ? cc1 : cc0;
#pragma unroll
            for (int nb = 0; nb < 8; ++nb) {
                int g = nb >> 1, uh = nb & 1;
#pragma unroll
                for (int ci = 0; ci < 4; ++ci) {
                    int p = ci & 1, rh = ci >> 1;
                    int n = g * 16 + uh * 8 + (tq << 1) + p;
                    float add = cc[n];
                    acc0[nb][ci] += fmaf(op[0][rh], wi0[n], add);
                    acc1[nb][ci] += fmaf(op[1][rh], wi0[n], add);
                }
            }

            // pointwise LSTM (tanh.approx)
            float hv[2][2][4];
#pragma unroll
            for (int rh = 0; rh < 2; ++rh)
#pragma unroll
                for (int q = 0; q < 4; ++q) {
                    int uh = q >> 1, p = q & 1;
                    int ci = rh * 2 + p;
                    {
                        float cn = fmaf(sig_hw(acc0[2 + uh][ci]), creg[0][rh][q],
                                        sig_hw(acc0[0 + uh][ci]) * tanh_hw(acc0[4 + uh][ci]));
                        creg[0][rh][q] = cn;
                        hv[0][rh][q] = sig_hw(acc0[6 + uh][ci]) * tanh_hw(cn);
                    }
                    {
                        float cn = fmaf(sig_hw(acc1[2 + uh][ci]), creg[1][rh][q],
                                        sig_hw(acc1[0 + uh][ci]) * tanh_hw(acc1[4 + uh][ci]));
                        creg[1][rh][q] = cn;
                        hv[1][rh][q] = sig_hw(acc1[6 + uh][ci]) * tanh_hw(cn);
                    }
                }

            // h store: one STG.128 per rt tile
#pragma unroll
            for (int r = 0; r < 2; ++r) {
                uint4 hp;
                hp.x = packh2(hv[r][0][0], hv[r][0][1]);
                hp.y = packh2(hv[r][1][0], hv[r][1][1]);
                hp.z = packh2(hv[r][0][2], hv[r][0][3]);
                hp.w = packh2(hv[r][1][2], hv[r][1][3]);
                *(uint4*)&N[(((g_rt0 + r) * 64 + ng) * 32 + lane) * 4] = hp;
            }

            // scalar head
#pragma unroll
            for (int r = 0; r < 2; ++r)
#pragma unroll
                for (int rh = 0; rh < 2; ++rh) {
                    float acc_s = 0.0f;
#pragma unroll
                    for (int q = 0; q < 4; ++q) {
                        int u = (q >> 1) * 8 + (tq << 1) + (q & 1);
                        acc_s = fmaf(hv[r][rh][q], wl[u], acc_s);
                    }
                    acc_s += __shfl_xor_sync(0xffffffffu, acc_s, 1);
                    acc_s += __shfl_xor_sync(0xffffffffu, acc_s, 2);
                    if (tq == 0) {
                        if (ng == 0) acc_s += blin0;
                        atomicAdd(&out[(rowbase + r * 16 + rh * 8 + gi) * T + t],
                                  acc_s);
                    }
                }
        }

        grid_barrier(bg);
    }
}

extern "C" void kernel_launch(void* const* d_in, const int* in_sizes, int n_in,
                              void* d_out, int out_size) {
    const float* h0   = (const float*)d_in[0];
    const float* c0   = (const float*)d_in[1];
    const float* Wih  = (const float*)d_in[2];
    const float* Whh  = (const float*)d_in[3];
    const float* bih  = (const float*)d_in[4];
    const float* bhh  = (const float*)d_in[5];
    const float* Wlin = (const float*)d_in[6];
    const float* blin = (const float*)d_in[7];
    float* out = (float*)d_out;

    int T = out_size / BSZ;
    if (T <= 0) return;

    cudaFuncSetAttribute(decoder_kernel,
                         cudaFuncAttributeMaxDynamicSharedMemorySize, SMEM_BYTES);
    decoder_kernel<<<NCTA, NTHR, SMEM_BYTES>>>(h0, c0, Wih, Whh, bih, bhh,
                                               Wlin, blin, out, T);
}